// round 3
// baseline (speedup 1.0000x reference)
#include <cuda_runtime.h>
#include <math.h>

// Scratch (static __device__ globals per the no-allocation rule).
__device__ __align__(16) float g_bufA[50000 * 64];
__device__ __align__(16) float g_bufB[50000 * 64];
__device__ __align__(16) float g_bufC[50000 * 64];
__device__ float g_deg[50000];
__device__ float g_dinv[50000];
__device__ int g_idx[1600000];  // converted int32 indices: [src | dst]
__device__ int g_is64;          // 1 if edge_index arrived as int64

// ---------------------------------------------------------------------------
// Dtype sniff: JAX silently downcasts jnp.int64 -> int32 unless x64 enabled,
// so edge_index may be int32 OR int64. If int64 (little-endian), the words at
// odd positions are the high halves of values < 50000 => all zero. If int32,
// they are random node ids — 4096 consecutive zeros is impossible.
// ---------------------------------------------------------------------------
__global__ void k_sniff(const int* __restrict__ w) {
    __shared__ int any_nz;
    if (threadIdx.x == 0) any_nz = 0;
    __syncthreads();
    int nz = 0;
    for (int k = threadIdx.x; k < 4096; k += blockDim.x)
        if (w[2 * k + 1] != 0) nz = 1;
    if (nz) atomicOr(&any_nz, 1);
    __syncthreads();
    if (threadIdx.x == 0) g_is64 = any_nz ? 0 : 1;
}

// Convert + clamp indices into int32. Deterministic; clamping prevents any
// OOB even if the sniff is wrong (yielding a rel_err signal, not a crash).
__global__ void k_convert(const void* __restrict__ ei, int total, int n) {
    int e = blockIdx.x * blockDim.x + threadIdx.x;
    if (e >= total) return;
    int v;
    if (g_is64)
        v = (int)((const long long*)ei)[e];
    else
        v = ((const int*)ei)[e];
    v = min(max(v, 0), n - 1);
    g_idx[e] = v;
}

// ---------------------------------------------------------------------------
// Degree / normalization
// ---------------------------------------------------------------------------
__global__ void k_deg_init(int n) {
    int i = blockIdx.x * blockDim.x + threadIdx.x;
    if (i < n) g_deg[i] = 1.0f;  // self-loop
}

__global__ void k_deg_edges(const int* __restrict__ dst, int E) {
    int e = blockIdx.x * blockDim.x + threadIdx.x;
    if (e < E) atomicAdd(&g_deg[dst[e]], 1.0f);
}

__global__ void k_dinv(int n) {
    int i = blockIdx.x * blockDim.x + threadIdx.x;
    if (i < n) g_dinv[i] = rsqrtf(g_deg[i]);
}

// ---------------------------------------------------------------------------
// Dense transform: H[i,:] = dinv[i] * (X[i,:] @ W), also init ACC = H
// (ACC init is the self-loop contribution, pre-scaled by dinv[src]).
// ---------------------------------------------------------------------------
template <int NOUT>
__global__ void k_gemm(const float* __restrict__ X, const float* __restrict__ W,
                       float* __restrict__ H, float* __restrict__ ACC, int n) {
    constexpr int CPT = NOUT / 4;  // columns per thread (4 threads per row)
    __shared__ float Ws[64 * (NOUT + 1)];
    __shared__ float Xs[64 * 65];

    int tid = threadIdx.x;
    for (int idx = tid; idx < 64 * NOUT; idx += 256) {
        int k = idx / NOUT, c = idx - k * NOUT;
        Ws[k * (NOUT + 1) + c] = W[idx];
    }
    int r0 = blockIdx.x * 64;
    for (int idx = tid; idx < 64 * 64; idx += 256) {
        int r = idx >> 6, c = idx & 63;
        int gr = r0 + r;
        Xs[r * 65 + c] = (gr < n) ? X[(size_t)gr * 64 + c] : 0.0f;
    }
    __syncthreads();

    int row = tid >> 2;
    int c0 = (tid & 3) * CPT;
    float acc[CPT];
#pragma unroll
    for (int j = 0; j < CPT; j++) acc[j] = 0.0f;
#pragma unroll
    for (int k = 0; k < 64; k++) {
        float xv = Xs[row * 65 + k];
        const float* wr = &Ws[k * (NOUT + 1) + c0];
#pragma unroll
        for (int j = 0; j < CPT; j++) acc[j] = fmaf(xv, wr[j], acc[j]);
    }
    int gr = r0 + row;
    if (gr < n) {
        float di = g_dinv[gr];
        size_t base = (size_t)gr * NOUT + c0;
#pragma unroll
        for (int j = 0; j < CPT; j++) {
            float v = acc[j] * di;
            H[base + j] = v;
            ACC[base + j] = v;
        }
    }
}

// ---------------------------------------------------------------------------
// Edge scatter: ACC[dst,:] += H[src,:] via vector reductions.
// NG = float4 groups per row (16 for D=64, 10 for D=40).
// ---------------------------------------------------------------------------
template <int NG>
__global__ void k_scatter(const int* __restrict__ src,
                          const int* __restrict__ dst,
                          const float* __restrict__ H, float* __restrict__ ACC,
                          int E) {
    long long tid = (long long)blockIdx.x * blockDim.x + threadIdx.x;
    int e = (int)(tid / NG);
    if (e >= E) return;
    int g = (int)(tid - (long long)e * NG);
    int s = src[e];
    int d = dst[e];
    const float4 v = *(const float4*)(H + (size_t)s * (NG * 4) + g * 4);
    float* p = ACC + (size_t)d * (NG * 4) + g * 4;
    asm volatile("red.global.add.v4.f32 [%0], {%1,%2,%3,%4};" ::"l"(p),
                 "f"(v.x), "f"(v.y), "f"(v.z), "f"(v.w)
                 : "memory");
}

// ---------------------------------------------------------------------------
// Finalize (layers 1,2): X[i,j] = relu(ACC[i,j]*dinv[i] + b[j]), float4-wide.
// ---------------------------------------------------------------------------
__global__ void k_finalize64(const float* __restrict__ ACC,
                             const float* __restrict__ b, float* __restrict__ X,
                             int n) {
    int tid = blockIdx.x * blockDim.x + threadIdx.x;
    if (tid >= n * 16) return;
    int i = tid >> 4;
    int jj = tid & 15;
    float di = g_dinv[i];
    float4 a = ((const float4*)ACC)[tid];
    float4 bb = ((const float4*)b)[jj];
    float4 o;
    o.x = fmaxf(fmaf(a.x, di, bb.x), 0.0f);
    o.y = fmaxf(fmaf(a.y, di, bb.y), 0.0f);
    o.z = fmaxf(fmaf(a.z, di, bb.z), 0.0f);
    o.w = fmaxf(fmaf(a.w, di, bb.w), 0.0f);
    ((float4*)X)[tid] = o;
}

// ---------------------------------------------------------------------------
// Finalize layer 3 + log_softmax over 40 classes. One warp per node.
// ---------------------------------------------------------------------------
__global__ void k_finalize3(const float* __restrict__ ACC,
                            const float* __restrict__ b,
                            float* __restrict__ out, int n) {
    int node = (blockIdx.x * blockDim.x + threadIdx.x) >> 5;
    int lane = threadIdx.x & 31;
    if (node >= n) return;
    float di = g_dinv[node];
    const float* row = ACC + (size_t)node * 40;
    float v1 = fmaxf(fmaf(row[lane], di, b[lane]), 0.0f);
    float v2 = (lane < 8) ? fmaxf(fmaf(row[lane + 32], di, b[lane + 32]), 0.0f)
                          : -3.4e38f;
    float m = fmaxf(v1, v2);
#pragma unroll
    for (int o = 16; o; o >>= 1) m = fmaxf(m, __shfl_xor_sync(0xffffffffu, m, o));
    float s = expf(v1 - m) + ((lane < 8) ? expf(v2 - m) : 0.0f);
#pragma unroll
    for (int o = 16; o; o >>= 1) s += __shfl_xor_sync(0xffffffffu, s, o);
    float lse = logf(s);
    float* orow = out + (size_t)node * 40;
    orow[lane] = v1 - m - lse;
    if (lane < 8) orow[lane + 32] = v2 - m - lse;
}

// ---------------------------------------------------------------------------
// Launch
// ---------------------------------------------------------------------------
extern "C" void kernel_launch(void* const* d_in, const int* in_sizes, int n_in,
                              void* d_out, int out_size) {
    const float* x = (const float*)d_in[0];
    const void* ei = d_in[1];
    const float* W1 = (const float*)d_in[2];
    const float* b1 = (const float*)d_in[3];
    const float* W2 = (const float*)d_in[4];
    const float* b2 = (const float*)d_in[5];
    const float* W3 = (const float*)d_in[6];
    const float* b3 = (const float*)d_in[7];
    float* out = (float*)d_out;

    int n = in_sizes[0] / 64;
    int E = in_sizes[1] / 2;

    static float* A = nullptr;
    static float* B = nullptr;
    static float* C = nullptr;
    static int* IDX = nullptr;
    if (!A) {
        cudaGetSymbolAddress((void**)&A, g_bufA);
        cudaGetSymbolAddress((void**)&B, g_bufB);
        cudaGetSymbolAddress((void**)&C, g_bufC);
        cudaGetSymbolAddress((void**)&IDX, g_idx);
    }
    const int* src = IDX;
    const int* dst = IDX + E;

    int nb = (n + 255) / 256;
    int eb = (E + 255) / 256;
    int cb = (2 * E + 255) / 256;
    int tiles = (n + 63) / 64;

    k_sniff<<<1, 1024>>>((const int*)ei);
    k_convert<<<cb, 256>>>(ei, 2 * E, n);
    k_deg_init<<<nb, 256>>>(n);
    k_deg_edges<<<eb, 256>>>(dst, E);
    k_dinv<<<nb, 256>>>(n);

    long long t16 = (long long)E * 16;
    int sb16 = (int)((t16 + 255) / 256);
    long long t10 = (long long)E * 10;
    int sb10 = (int)((t10 + 255) / 256);
    int fb = (n * 16 + 255) / 256;
    int f3b = (n * 32 + 255) / 256;

    // Layer 1
    k_gemm<64><<<tiles, 256>>>(x, W1, A, B, n);
    k_scatter<16><<<sb16, 256>>>(src, dst, A, B, E);
    k_finalize64<<<fb, 256>>>(B, b1, C, n);
    // Layer 2
    k_gemm<64><<<tiles, 256>>>(C, W2, A, B, n);
    k_scatter<16><<<sb16, 256>>>(src, dst, A, B, E);
    k_finalize64<<<fb, 256>>>(B, b2, C, n);
    // Layer 3 (40 classes)
    k_gemm<40><<<tiles, 256>>>(C, W3, A, B, n);
    k_scatter<10><<<sb10, 256>>>(src, dst, A, B, E);
    k_finalize3<<<f3b, 256>>>(B, b3, out, n);
}

// round 4
// speedup vs baseline: 1.5909x; 1.5909x over previous
#include <cuda_runtime.h>
#include <math.h>

// ---- static scratch (no-allocation rule) ----
__device__ __align__(16) float g_bufA[50000 * 64];  // H (pre-scaled transform)
__device__ __align__(16) float g_bufB[50000 * 64];  // X ping
__device__ __align__(16) float g_bufC[50000 * 64];  // X pong
__device__ float g_dinv[50000];
__device__ int g_idx[1600000];   // converted int32 indices: [src | dst]
__device__ int g_cnt[50000];     // in-degree histogram
__device__ int g_rowptr[50001];  // CSR row pointers (by dst)
__device__ int g_cursor[50000];  // fill cursors
__device__ int g_col[800000];    // CSR column (src) ids
__device__ int g_is64;

// ---------------------------------------------------------------------------
// Dtype sniff: int64 high words (odd positions) are all zero for ids < 50000;
// int32 data has random ids there.
// ---------------------------------------------------------------------------
__global__ void k_sniff(const int* __restrict__ w) {
    __shared__ int any_nz;
    if (threadIdx.x == 0) any_nz = 0;
    __syncthreads();
    int nz = 0;
    for (int k = threadIdx.x; k < 4096; k += blockDim.x)
        if (w[2 * k + 1] != 0) nz = 1;
    if (nz) atomicOr(&any_nz, 1);
    __syncthreads();
    if (threadIdx.x == 0) g_is64 = any_nz ? 0 : 1;
}

__global__ void k_zero_cnt(int n) {
    int i = blockIdx.x * blockDim.x + threadIdx.x;
    if (i < n) g_cnt[i] = 0;
}

// Convert + clamp indices; also histogram in-degrees for the dst half.
__global__ void k_convert(const void* __restrict__ ei, int E, int n) {
    int e = blockIdx.x * blockDim.x + threadIdx.x;
    if (e >= 2 * E) return;
    int v;
    if (g_is64)
        v = (int)((const long long*)ei)[e];
    else
        v = ((const int*)ei)[e];
    v = min(max(v, 0), n - 1);
    g_idx[e] = v;
    if (e >= E) atomicAdd(&g_cnt[v], 1);
}

__global__ void k_dinv(int n) {
    int i = blockIdx.x * blockDim.x + threadIdx.x;
    if (i < n) g_dinv[i] = rsqrtf((float)g_cnt[i] + 1.0f);  // + self-loop
}

// Single-block exclusive scan of g_cnt -> g_rowptr (+ cursor copy).
__global__ void k_scan(int n) {
    __shared__ int partial[1024];
    int t = threadIdx.x;
    int per = (n + 1023) / 1024;
    int lo = t * per, hi = min(lo + per, n);
    int s = 0;
    for (int i = lo; i < hi; i++) s += g_cnt[i];
    partial[t] = s;
    __syncthreads();
    for (int off = 1; off < 1024; off <<= 1) {
        int v = partial[t];
        int add = (t >= off) ? partial[t - off] : 0;
        __syncthreads();
        partial[t] = v + add;
        __syncthreads();
    }
    int ex = (t == 0) ? 0 : partial[t - 1];
    for (int i = lo; i < hi; i++) {
        g_rowptr[i] = ex;
        g_cursor[i] = ex;
        ex += g_cnt[i];
    }
    if (t == 0) g_rowptr[n] = partial[1023];
}

__global__ void k_fill(int E) {
    int e = blockIdx.x * blockDim.x + threadIdx.x;
    if (e >= E) return;
    int s = g_idx[e];
    int d = g_idx[E + e];
    int pos = atomicAdd(&g_cursor[d], 1);
    g_col[pos] = s;
}

// ---------------------------------------------------------------------------
// GEMM 64x64: H[i,:] = dinv[i] * (X[i,:] @ W). 4x4 register blocking.
// Block = 256 threads -> 64-row x 64-col tile.
// ---------------------------------------------------------------------------
__global__ __launch_bounds__(256) void k_gemm64(const float* __restrict__ X,
                                                const float* __restrict__ W,
                                                float* __restrict__ H, int n) {
    __shared__ float Xs[64 * 64];  // transposed: Xs[k*64 + r] = X[r][k]
    __shared__ float Ws[64 * 64];  // Ws[k*64 + c]
    int tid = threadIdx.x;
    int rbase = blockIdx.x * 64;

    // load W (row-major k x c) as float4
    for (int i = tid; i < 1024; i += 256)
        ((float4*)Ws)[i] = ((const float4*)W)[i];
    // load X tile, store transposed
    for (int i = tid; i < 1024; i += 256) {
        int r = i >> 4;           // 0..63
        int c4 = (i & 15) << 2;   // 0..60
        int gr = rbase + r;
        float4 v = (gr < n) ? ((const float4*)(X + (size_t)gr * 64))[i & 15]
                            : make_float4(0.f, 0.f, 0.f, 0.f);
        Xs[(c4 + 0) * 64 + r] = v.x;
        Xs[(c4 + 1) * 64 + r] = v.y;
        Xs[(c4 + 2) * 64 + r] = v.z;
        Xs[(c4 + 3) * 64 + r] = v.w;
    }
    __syncthreads();

    int r0 = (tid >> 4) << 2;  // 0..60
    int c0 = (tid & 15) << 2;  // 0..60
    float acc[4][4];
#pragma unroll
    for (int i = 0; i < 4; i++)
#pragma unroll
        for (int j = 0; j < 4; j++) acc[i][j] = 0.f;

#pragma unroll 8
    for (int k = 0; k < 64; k++) {
        float4 xa = *(const float4*)&Xs[k * 64 + r0];
        float4 wa = *(const float4*)&Ws[k * 64 + c0];
        float xr[4] = {xa.x, xa.y, xa.z, xa.w};
        float wr[4] = {wa.x, wa.y, wa.z, wa.w};
#pragma unroll
        for (int i = 0; i < 4; i++)
#pragma unroll
            for (int j = 0; j < 4; j++) acc[i][j] = fmaf(xr[i], wr[j], acc[i][j]);
    }

#pragma unroll
    for (int i = 0; i < 4; i++) {
        int gr = rbase + r0 + i;
        if (gr < n) {
            float di = g_dinv[gr];
            float4 o = make_float4(acc[i][0] * di, acc[i][1] * di,
                                   acc[i][2] * di, acc[i][3] * di);
            *(float4*)(H + (size_t)gr * 64 + c0) = o;
        }
    }
}

// ---------------------------------------------------------------------------
// GEMM 64x40 (layer 3): simple version, writes H only.
// ---------------------------------------------------------------------------
__global__ __launch_bounds__(256) void k_gemm40(const float* __restrict__ X,
                                                const float* __restrict__ W,
                                                float* __restrict__ H, int n) {
    __shared__ float Ws[64 * 41];
    __shared__ float Xs[64 * 65];
    int tid = threadIdx.x;
    for (int idx = tid; idx < 64 * 40; idx += 256) {
        int k = idx / 40, c = idx - k * 40;
        Ws[k * 41 + c] = W[idx];
    }
    int r0 = blockIdx.x * 64;
    for (int idx = tid; idx < 64 * 64; idx += 256) {
        int r = idx >> 6, c = idx & 63;
        int gr = r0 + r;
        Xs[r * 65 + c] = (gr < n) ? X[(size_t)gr * 64 + c] : 0.0f;
    }
    __syncthreads();

    int row = tid >> 2;
    int c0 = (tid & 3) * 10;
    float acc[10];
#pragma unroll
    for (int j = 0; j < 10; j++) acc[j] = 0.0f;
#pragma unroll
    for (int k = 0; k < 64; k++) {
        float xv = Xs[row * 65 + k];
        const float* wr = &Ws[k * 41 + c0];
#pragma unroll
        for (int j = 0; j < 10; j++) acc[j] = fmaf(xv, wr[j], acc[j]);
    }
    int gr = r0 + row;
    if (gr < n) {
        float di = g_dinv[gr];
        size_t base = (size_t)gr * 40 + c0;
#pragma unroll
        for (int j = 0; j < 10; j++) H[base + j] = acc[j] * di;
    }
}

// ---------------------------------------------------------------------------
// CSR gather, D=64: one warp per node. Fused finalize (dinv, bias, relu).
// Lane l owns elements (2l, 2l+1) => warp reads 256B coalesced per edge.
// ---------------------------------------------------------------------------
__global__ __launch_bounds__(256) void k_gather64(const float* __restrict__ H,
                                                  const float* __restrict__ b,
                                                  float* __restrict__ X, int n) {
    int warp = (blockIdx.x * blockDim.x + threadIdx.x) >> 5;
    int lane = threadIdx.x & 31;
    if (warp >= n) return;
    int v = warp;
    const float2* H2 = (const float2*)H;
    float2 a0 = H2[(size_t)v * 32 + lane];  // self-loop
    float2 a1 = make_float2(0.f, 0.f);
    int rs = g_rowptr[v], re = g_rowptr[v + 1];
    for (int base = rs; base < re; base += 32) {
        int m = min(32, re - base);
        int cs = (lane < m) ? g_col[base + lane] : 0;
        int j = 0;
        for (; j + 2 <= m; j += 2) {
            int s0 = __shfl_sync(0xffffffffu, cs, j);
            int s1 = __shfl_sync(0xffffffffu, cs, j + 1);
            float2 h0 = H2[(size_t)s0 * 32 + lane];
            float2 h1 = H2[(size_t)s1 * 32 + lane];
            a0.x += h0.x; a0.y += h0.y;
            a1.x += h1.x; a1.y += h1.y;
        }
        if (j < m) {
            int s = __shfl_sync(0xffffffffu, cs, j);
            float2 h = H2[(size_t)s * 32 + lane];
            a0.x += h.x; a0.y += h.y;
        }
    }
    float di = g_dinv[v];
    float o0 = fmaxf(fmaf(a0.x + a1.x, di, b[2 * lane + 0]), 0.f);
    float o1 = fmaxf(fmaf(a0.y + a1.y, di, b[2 * lane + 1]), 0.f);
    ((float2*)X)[(size_t)v * 32 + lane] = make_float2(o0, o1);
}

// ---------------------------------------------------------------------------
// CSR gather, D=40 + fused relu + log_softmax. Lane l<20 owns (2l, 2l+1).
// ---------------------------------------------------------------------------
__global__ __launch_bounds__(256) void k_gather40(const float* __restrict__ H,
                                                  const float* __restrict__ b,
                                                  float* __restrict__ out, int n) {
    int warp = (blockIdx.x * blockDim.x + threadIdx.x) >> 5;
    int lane = threadIdx.x & 31;
    if (warp >= n) return;
    int v = warp;
    bool act = lane < 20;
    const float2* H2 = (const float2*)H;
    float2 a0 = act ? H2[(size_t)v * 20 + lane] : make_float2(0.f, 0.f);
    float2 a1 = make_float2(0.f, 0.f);
    int rs = g_rowptr[v], re = g_rowptr[v + 1];
    for (int base = rs; base < re; base += 32) {
        int m = min(32, re - base);
        int cs = (lane < m) ? g_col[base + lane] : 0;
        int j = 0;
        for (; j + 2 <= m; j += 2) {
            int s0 = __shfl_sync(0xffffffffu, cs, j);
            int s1 = __shfl_sync(0xffffffffu, cs, j + 1);
            if (act) {
                float2 h0 = H2[(size_t)s0 * 20 + lane];
                float2 h1 = H2[(size_t)s1 * 20 + lane];
                a0.x += h0.x; a0.y += h0.y;
                a1.x += h1.x; a1.y += h1.y;
            }
        }
        if (j < m) {
            int s = __shfl_sync(0xffffffffu, cs, j);
            if (act) {
                float2 h = H2[(size_t)s * 20 + lane];
                a0.x += h.x; a0.y += h.y;
            }
        }
    }
    float di = g_dinv[v];
    float v0 = act ? fmaxf(fmaf(a0.x + a1.x, di, b[2 * lane + 0]), 0.f) : -3.4e38f;
    float v1 = act ? fmaxf(fmaf(a0.y + a1.y, di, b[2 * lane + 1]), 0.f) : -3.4e38f;
    float mx = fmaxf(v0, v1);
#pragma unroll
    for (int o = 16; o; o >>= 1) mx = fmaxf(mx, __shfl_xor_sync(0xffffffffu, mx, o));
    float sm = act ? (expf(v0 - mx) + expf(v1 - mx)) : 0.f;
#pragma unroll
    for (int o = 16; o; o >>= 1) sm += __shfl_xor_sync(0xffffffffu, sm, o);
    float lse = logf(sm);
    if (act) {
        float* orow = out + (size_t)v * 40;
        orow[2 * lane + 0] = v0 - mx - lse;
        orow[2 * lane + 1] = v1 - mx - lse;
    }
}

// ---------------------------------------------------------------------------
// Launch
// ---------------------------------------------------------------------------
extern "C" void kernel_launch(void* const* d_in, const int* in_sizes, int n_in,
                              void* d_out, int out_size) {
    const float* x = (const float*)d_in[0];
    const void* ei = d_in[1];
    const float* W1 = (const float*)d_in[2];
    const float* b1 = (const float*)d_in[3];
    const float* W2 = (const float*)d_in[4];
    const float* b2 = (const float*)d_in[5];
    const float* W3 = (const float*)d_in[6];
    const float* b3 = (const float*)d_in[7];
    float* out = (float*)d_out;

    int n = in_sizes[0] / 64;
    int E = in_sizes[1] / 2;

    static float* A = nullptr;
    static float* B = nullptr;
    static float* C = nullptr;
    if (!A) {
        cudaGetSymbolAddress((void**)&A, g_bufA);
        cudaGetSymbolAddress((void**)&B, g_bufB);
        cudaGetSymbolAddress((void**)&C, g_bufC);
    }

    int nb = (n + 255) / 256;
    int eb = (E + 255) / 256;
    int cb = (2 * E + 255) / 256;
    int tiles = (n + 63) / 64;
    int gb = (n * 32 + 255) / 256;  // warp-per-node grids

    // CSR build
    k_sniff<<<1, 1024>>>((const int*)ei);
    k_zero_cnt<<<nb, 256>>>(n);
    k_convert<<<cb, 256>>>(ei, E, n);
    k_dinv<<<nb, 256>>>(n);
    k_scan<<<1, 1024>>>(n);
    k_fill<<<eb, 256>>>(E);

    // Layer 1
    k_gemm64<<<tiles, 256>>>(x, W1, A, n);
    k_gather64<<<gb, 256>>>(A, b1, C, n);
    // Layer 2
    k_gemm64<<<tiles, 256>>>(C, W2, A, n);
    k_gather64<<<gb, 256>>>(A, b2, B, n);
    // Layer 3
    k_gemm40<<<tiles, 256>>>(B, W3, A, n);
    k_gather40<<<gb, 256>>>(A, b3, out, n);
}